// round 8
// baseline (speedup 1.0000x reference)
#include <cuda_runtime.h>
#include <math.h>

#define D_FEAT 128
#define FULL 0xffffffffu
#define MAX_NODES 100000

// Scratch: per-node L2 norms of feature rows (allocation-free __device__ global).
__device__ float g_norms[MAX_NODES];

// ---------------------------------------------------------------------------
// Transpose-reduce: lane l holds p[k] = partial of value k. After this, lane l
// holds the full sum for value l in p[0]. Costs 16+8+4+2+1 = 31 shuffles
// (vs 32 * 5 = 160 for per-value butterflies).
// ---------------------------------------------------------------------------
__device__ __forceinline__ void warp_transpose_reduce32(float (&p)[32], int lane) {
#pragma unroll
    for (int o = 16; o >= 1; o >>= 1) {
        bool hi = (lane & o) != 0;
#pragma unroll
        for (int i = 0; i < o; i++) {
            float send = hi ? p[i] : p[i + o];
            float recv = __shfl_xor_sync(FULL, send, o);
            p[i] = (hi ? p[i + o] : p[i]) + recv;
        }
    }
    // p[0] on lane l == sum over all lanes of original p[l]
}

// ---------------------------------------------------------------------------
// Kernel 1: per-node norms. Each warp computes 32 CONSECUTIVE node norms via
// one transpose-reduce; store is a single coalesced STG.
// ---------------------------------------------------------------------------
__global__ void __launch_bounds__(256) norms_kernel(const float* __restrict__ feats,
                                                    int n_nodes) {
    int warp = (blockIdx.x * blockDim.x + threadIdx.x) >> 5;
    int lane = threadIdx.x & 31;
    int base = warp * 32;
    if (base >= n_nodes) return;

    float p[32];
#pragma unroll
    for (int k = 0; k < 32; k++) {
        int idx = base + k;
        if (idx < n_nodes) {
            const float4* row = (const float4*)(feats + (size_t)idx * D_FEAT);
            float4 v = row[lane];
            p[k] = v.x * v.x + v.y * v.y + v.z * v.z + v.w * v.w;
        } else {
            p[k] = 0.0f;
        }
    }
    warp_transpose_reduce32(p, lane);
    int idx = base + lane;
    if (idx < n_nodes) g_norms[idx] = sqrtf(p[0]);
}

__device__ __forceinline__ unsigned f2ord(float f) {
    unsigned u = __float_as_uint(f);
    return (u & 0x80000000u) ? ~u : (u | 0x80000000u);
}

// ---------------------------------------------------------------------------
// Kernel 2: per-batch-node cosine top-k aggregation. Warp per batch node.
// Lane l holds float4 chunk l of the center row; each neighbor row is one
// coalesced warp-wide LDG.128 (512B contiguous). Partial dots accumulate in a
// 32-reg array; one transpose-reduce delivers sim_k to lane k.
// ---------------------------------------------------------------------------
__global__ void __launch_bounds__(256) agg_kernel(const float* __restrict__ feats,
                                                  const int* __restrict__ nodes,
                                                  const int* __restrict__ neighs,
                                                  const int* __restrict__ ns_ptr,
                                                  float* __restrict__ out,
                                                  int B, int K) {
    int warp = (blockIdx.x * blockDim.x + threadIdx.x) >> 5;
    int lane = threadIdx.x & 31;
    if (warp >= B) return;

    int ns = ns_ptr ? __ldg(ns_ptr) : 10;
    if (ns > K) ns = K;

    int node = __ldg(&nodes[warp]);
    int myneigh = (lane < K) ? __ldg(&neighs[(size_t)warp * K + lane]) : 0;
    float mynorm = g_norms[myneigh];
    float cnorm = g_norms[node];

    const float4* crow = (const float4*)(feats + (size_t)node * D_FEAT);
    float4 c = crow[lane];

    float sim;
    if (K == 32) {
        // --- partial dots for all 32 neighbors, no per-neighbor reduction ---
        float p[32];
#pragma unroll
        for (int k = 0; k < 32; k++) {
            int idx = __shfl_sync(FULL, myneigh, k);
            const float4* row = (const float4*)(feats + (size_t)idx * D_FEAT);
            float4 v = row[lane];
            p[k] = v.x * c.x + v.y * c.y + v.z * c.z + v.w * c.w;
        }
        warp_transpose_reduce32(p, lane);       // 31 shfl total
        sim = p[0] / (cnorm * mynorm);          // sim for neighbor `lane`
    } else {
        // generic fallback: per-neighbor butterfly
        float mydot = 0.0f;
        for (int k = 0; k < K; k++) {
            int idx = __shfl_sync(FULL, myneigh, k);
            const float4* row = (const float4*)(feats + (size_t)idx * D_FEAT);
            float4 v = row[lane];
            float pp = v.x * c.x + v.y * c.y + v.z * c.z + v.w * c.w;
#pragma unroll
            for (int o = 16; o; o >>= 1) pp += __shfl_xor_sync(FULL, pp, o);
            if (lane == k) mydot = pp;
        }
        sim = mydot / (cnorm * mynorm);
    }

    // --- top-ns selection: redux.max on order key, lowest-index tie-break ---
    unsigned key = f2ord(sim);
    if (lane >= K) key = 0u;
    unsigned sel = 0u;
    for (int i = 0; i < ns; i++) {
        unsigned m = __reduce_max_sync(FULL, key);
        unsigned b = __ballot_sync(FULL, key == m);
        int kk = __ffs(b) - 1;
        sel |= 1u << kk;
        if (lane == kk) key = 0u;
    }

    // --- mean of selected rows (re-gather: rows are L1-hot) + relu ---
    float4 acc = make_float4(0.f, 0.f, 0.f, 0.f);
    unsigned m2 = sel;
    while (m2) {
        int k = __ffs(m2) - 1;
        m2 &= m2 - 1;
        int idx = __shfl_sync(FULL, myneigh, k);
        const float4* row = (const float4*)(feats + (size_t)idx * D_FEAT);
        float4 v = row[lane];
        acc.x += v.x; acc.y += v.y; acc.z += v.z; acc.w += v.w;
    }
    float inv = 1.0f / (float)ns;
    float4 o;
    o.x = fmaxf(acc.x * inv, 0.0f);
    o.y = fmaxf(acc.y * inv, 0.0f);
    o.z = fmaxf(acc.z * inv, 0.0f);
    o.w = fmaxf(acc.w * inv, 0.0f);
    ((float4*)(out + (size_t)warp * D_FEAT))[lane] = o;
}

// ---------------------------------------------------------------------------
// kernel_launch: graph-capturable, allocation-free.
// ---------------------------------------------------------------------------
extern "C" void kernel_launch(void* const* d_in, const int* in_sizes, int n_in,
                              void* d_out, int out_size) {
    const float* feats = (const float*)d_in[0];
    const int* nodes = (const int*)d_in[1];
    const int* neighs = (const int*)d_in[2];
    const int* ns_ptr = (n_in > 3) ? (const int*)d_in[3] : nullptr;

    int n_nodes = in_sizes[0] / D_FEAT;
    if (n_nodes > MAX_NODES) n_nodes = MAX_NODES;
    int B = in_sizes[1];
    int K = (B > 0) ? (in_sizes[2] / B) : 0;

    // norms: one warp per 32 nodes
    int norm_warps = (n_nodes + 31) / 32;
    int norm_blocks = (norm_warps * 32 + 255) / 256;
    norms_kernel<<<norm_blocks, 256>>>(feats, n_nodes);

    int agg_blocks = (B * 32 + 255) / 256;
    agg_kernel<<<agg_blocks, 256>>>(feats, nodes, neighs, ns_ptr,
                                    (float*)d_out, B, K);
}

// round 10
// speedup vs baseline: 1.2886x; 1.2886x over previous
#include <cuda_runtime.h>
#include <math.h>

#define D_FEAT 128
#define FULL 0xffffffffu
#define MAX_NODES 100000

// Scratch: per-node L2 norms of feature rows (allocation-free __device__ global).
__device__ float g_norms[MAX_NODES];

// ---------------------------------------------------------------------------
// Kernel 1: precompute ||features[n]|| for all nodes. Warp per node.
// (R6 version: DRAM-streaming bound, ~7us — near floor. Do not touch.)
// ---------------------------------------------------------------------------
__global__ void __launch_bounds__(256) norms_kernel(const float* __restrict__ feats,
                                                    int n_nodes) {
    int warp = (blockIdx.x * blockDim.x + threadIdx.x) >> 5;
    int lane = threadIdx.x & 31;
    if (warp >= n_nodes) return;
    const float4* row = (const float4*)(feats + (size_t)warp * D_FEAT);
    float4 v = row[lane];
    float s = v.x * v.x + v.y * v.y + v.z * v.z + v.w * v.w;
#pragma unroll
    for (int o = 16; o; o >>= 1) s += __shfl_xor_sync(FULL, s, o);
    if (lane == 0) g_norms[warp] = sqrtf(s);
}

__device__ __forceinline__ unsigned f2ord(float f) {
    unsigned u = __float_as_uint(f);
    return (u & 0x80000000u) ? ~u : (u | 0x80000000u);
}

__device__ __forceinline__ float dot4(float4 v, float4 c) {
    return v.x * c.x + v.y * c.y + v.z * c.z + v.w * c.w;
}

// ---------------------------------------------------------------------------
// Kernel 2: per-batch-node cosine top-k aggregation. Warp per batch node.
// Lane l holds float4 chunk l of center; each neighbor row is one coalesced
// warp-wide LDG.128 (512B contiguous). Dot reductions use a groups-of-8
// transpose-reduce: 9 shfl per 8 neighbors (vs 40 for butterflies), with only
// p[8] live -> low register pressure.
// ---------------------------------------------------------------------------
__global__ void __launch_bounds__(256) agg_kernel(const float* __restrict__ feats,
                                                  const int* __restrict__ nodes,
                                                  const int* __restrict__ neighs,
                                                  const int* __restrict__ ns_ptr,
                                                  float* __restrict__ out,
                                                  int B, int K) {
    int warp = (blockIdx.x * blockDim.x + threadIdx.x) >> 5;
    int lane = threadIdx.x & 31;
    if (warp >= B) return;

    int ns = ns_ptr ? __ldg(ns_ptr) : 10;
    if (ns > K) ns = K;

    int node = __ldg(&nodes[warp]);
    int myneigh = (lane < K) ? __ldg(&neighs[(size_t)warp * K + lane]) : 0;
    float mynorm = g_norms[myneigh];   // lane k's neighbor norm (scattered, small)
    float cnorm = g_norms[node];

    const float4* crow = (const float4*)(feats + (size_t)node * D_FEAT);
    float4 c = crow[lane];

    float sim;
    if (K == 32) {
        const int4* nb = (const int4*)(neighs + (size_t)warp * 32);
        float sims4[4];   // per group: reduced dot for neighbor g*8 + ((lane>>2)&7)
        bool h16 = (lane & 16) != 0;
        bool h8  = (lane & 8)  != 0;
        bool h4  = (lane & 4)  != 0;
#pragma unroll
        for (int g = 0; g < 4; g++) {
            // 8 neighbor indices via 2 uniform LDG.128 (all lanes same addr)
            int4 ia = __ldg(&nb[2 * g]);
            int4 ib = __ldg(&nb[2 * g + 1]);
            float p[8];
            p[0] = dot4(((const float4*)(feats + (size_t)ia.x * D_FEAT))[lane], c);
            p[1] = dot4(((const float4*)(feats + (size_t)ia.y * D_FEAT))[lane], c);
            p[2] = dot4(((const float4*)(feats + (size_t)ia.z * D_FEAT))[lane], c);
            p[3] = dot4(((const float4*)(feats + (size_t)ia.w * D_FEAT))[lane], c);
            p[4] = dot4(((const float4*)(feats + (size_t)ib.x * D_FEAT))[lane], c);
            p[5] = dot4(((const float4*)(feats + (size_t)ib.y * D_FEAT))[lane], c);
            p[6] = dot4(((const float4*)(feats + (size_t)ib.z * D_FEAT))[lane], c);
            p[7] = dot4(((const float4*)(feats + (size_t)ib.w * D_FEAT))[lane], c);
            // stage o=16: 8 -> 4 values (4 shfl)
#pragma unroll
            for (int i = 0; i < 4; i++) {
                float send = h16 ? p[i] : p[i + 4];
                float recv = __shfl_xor_sync(FULL, send, 16);
                p[i] = (h16 ? p[i + 4] : p[i]) + recv;
            }
            // stage o=8: 4 -> 2 (2 shfl)
#pragma unroll
            for (int i = 0; i < 2; i++) {
                float send = h8 ? p[i] : p[i + 2];
                float recv = __shfl_xor_sync(FULL, send, 8);
                p[i] = (h8 ? p[i + 2] : p[i]) + recv;
            }
            // stage o=4: 2 -> 1 (1 shfl)
            {
                float send = h4 ? p[0] : p[1];
                float recv = __shfl_xor_sync(FULL, send, 4);
                p[0] = (h4 ? p[1] : p[0]) + recv;
            }
            // finish over bits {1,0} (2 shfl)
            p[0] += __shfl_xor_sync(FULL, p[0], 2);
            p[0] += __shfl_xor_sync(FULL, p[0], 1);
            sims4[g] = p[0];   // dot for neighbor g*8 + ((lane>>2)&7)
        }
        // redistribute: lane k wants neighbor k = (k>>3)*8 + (k&7),
        // held by lane (k&7)<<2 in sims4[k>>3]. 4 shfl + selects.
        int src = (lane & 7) << 2;
        float s0 = __shfl_sync(FULL, sims4[0], src);
        float s1 = __shfl_sync(FULL, sims4[1], src);
        float s2 = __shfl_sync(FULL, sims4[2], src);
        float s3 = __shfl_sync(FULL, sims4[3], src);
        int gk = lane >> 3;
        float d01 = (gk & 1) ? s1 : s0;
        float d23 = (gk & 1) ? s3 : s2;
        float dotk = (gk & 2) ? d23 : d01;
        sim = dotk / (cnorm * mynorm);
    } else {
        // generic fallback: per-neighbor butterfly
        float mydot = 0.0f;
        for (int k = 0; k < K; k++) {
            int idx = __shfl_sync(FULL, myneigh, k);
            const float4* row = (const float4*)(feats + (size_t)idx * D_FEAT);
            float4 v = row[lane];
            float pp = dot4(v, c);
#pragma unroll
            for (int o = 16; o; o >>= 1) pp += __shfl_xor_sync(FULL, pp, o);
            if (lane == k) mydot = pp;
        }
        sim = mydot / (cnorm * mynorm);
    }

    // --- top-ns selection: redux.max on order key, lowest-index tie-break ---
    unsigned key = f2ord(sim);
    if (lane >= K) key = 0u;
    unsigned sel = 0u;
    for (int i = 0; i < ns; i++) {
        unsigned m = __reduce_max_sync(FULL, key);
        unsigned b = __ballot_sync(FULL, key == m);
        int kk = __ffs(b) - 1;
        sel |= 1u << kk;
        if (lane == kk) key = 0u;
    }

    // --- mean of selected rows (re-gather: rows are L1-hot) + relu ---
    float4 acc = make_float4(0.f, 0.f, 0.f, 0.f);
    unsigned m2 = sel;
    while (m2) {
        int k = __ffs(m2) - 1;
        m2 &= m2 - 1;
        int idx = __shfl_sync(FULL, myneigh, k);
        const float4* row = (const float4*)(feats + (size_t)idx * D_FEAT);
        float4 v = row[lane];
        acc.x += v.x; acc.y += v.y; acc.z += v.z; acc.w += v.w;
    }
    float inv = 1.0f / (float)ns;
    float4 o;
    o.x = fmaxf(acc.x * inv, 0.0f);
    o.y = fmaxf(acc.y * inv, 0.0f);
    o.z = fmaxf(acc.z * inv, 0.0f);
    o.w = fmaxf(acc.w * inv, 0.0f);
    ((float4*)(out + (size_t)warp * D_FEAT))[lane] = o;
}

// ---------------------------------------------------------------------------
// kernel_launch: graph-capturable, allocation-free.
// ---------------------------------------------------------------------------
extern "C" void kernel_launch(void* const* d_in, const int* in_sizes, int n_in,
                              void* d_out, int out_size) {
    const float* feats = (const float*)d_in[0];
    const int* nodes = (const int*)d_in[1];
    const int* neighs = (const int*)d_in[2];
    const int* ns_ptr = (n_in > 3) ? (const int*)d_in[3] : nullptr;

    int n_nodes = in_sizes[0] / D_FEAT;
    if (n_nodes > MAX_NODES) n_nodes = MAX_NODES;
    int B = in_sizes[1];
    int K = (B > 0) ? (in_sizes[2] / B) : 0;

    int norm_blocks = (n_nodes * 32 + 255) / 256;
    norms_kernel<<<norm_blocks, 256>>>(feats, n_nodes);

    int agg_blocks = (B * 32 + 255) / 256;
    agg_kernel<<<agg_blocks, 256>>>(feats, nodes, neighs, ns_ptr,
                                    (float*)d_out, B, K);
}